// round 16
// baseline (speedup 1.0000x reference)
#include <cuda_runtime.h>
#include <cuda_fp16.h>
#include <cstdint>

// APPNP propagation on GB300 (sm_103a).
// h0 = x; for k in 0..9: h_{k+1} = 0.9 * A @ h_k + 0.1 * x
//
// R16: ncu showed 57MB/iter of DRAM traffic -> L2 thrash (96MB footprint vs
// 126MB L2, random 256B gathers + dirty writebacks). x16 was dead weight
// after iteration 1 (alpha comes from the fp8 copy), so convert_x now writes
// the fp16 x directly into h16b and the chain ping-pongs two buffers only.
// Footprint 96 -> 70MB. Numerically identical to R15 (rel_err 4.3e-4).
// Core: two rows per warp (one LDG.128 gather serves two edges), fp16
// intermediates (stored_k = h_k * 4^-k), fp8 alpha*x source, cv 4B/edge
// (col 18b | w 14b fixed-point), single-pass bucketed CSR.

#define N_NODES 100000
#define D_FEAT 128
#define ROW_CAP 64

#define W_MAX 0.225f              // 0.9 * 0.25 * val, val in [0,1)
#define WQ_SCALE 16383.0f
#define COL_MASK 0x3FFFFu

__device__ uint4    g_h16a[(size_t)N_NODES * 16];   // fp16x8 per lane-chunk
__device__ uint4    g_h16b[(size_t)N_NODES * 16];   // also holds fp16(x) at start
__device__ uint2    g_x8  [(size_t)N_NODES * 16];   // fp8x8 per lane-chunk
__device__ int      g_len [N_NODES];
__device__ unsigned g_cv  [(size_t)N_NODES * ROW_CAP];  // col | (wq << 18)

// ---- fp8 helpers (e4m3) ----
__device__ __forceinline__ unsigned pack_f8x4(float f0, float f1, float f2, float f3)
{
    unsigned short s01, s23;
    asm("cvt.rn.satfinite.e4m3x2.f32 %0, %1, %2;" : "=h"(s01) : "f"(f1), "f"(f0));
    asm("cvt.rn.satfinite.e4m3x2.f32 %0, %1, %2;" : "=h"(s23) : "f"(f3), "f"(f2));
    return (unsigned)s01 | ((unsigned)s23 << 16);
}

__device__ __forceinline__ float4 unpack_f8x4(unsigned u)
{
    unsigned short s01 = (unsigned short)(u & 0xffff);
    unsigned short s23 = (unsigned short)(u >> 16);
    unsigned h01, h23;
    asm("cvt.rn.f16x2.e4m3x2 %0, %1;" : "=r"(h01) : "h"(s01));
    asm("cvt.rn.f16x2.e4m3x2 %0, %1;" : "=r"(h23) : "h"(s23));
    float2 a = __half22float2(*(__half2*)&h01);
    float2 b = __half22float2(*(__half2*)&h23);
    return make_float4(a.x, a.y, b.x, b.y);
}

// ---- x fp32 -> fp16 (into h16b) + fp8; also zeroes len[] ----
__global__ __launch_bounds__(256) void convert_x_kernel(
    const float4* __restrict__ x4, uint4* __restrict__ h16b,
    uint2* __restrict__ x8, int* __restrict__ len, int n8)
{
    int i = blockIdx.x * blockDim.x + threadIdx.x;
    if (i < N_NODES) len[i] = 0;
    if (i >= n8) return;
    float4 va = x4[2 * i];
    float4 vb = x4[2 * i + 1];
    __half2 h0 = __floats2half2_rn(va.x, va.y);
    __half2 h1 = __floats2half2_rn(va.z, va.w);
    __half2 h2 = __floats2half2_rn(vb.x, vb.y);
    __half2 h3 = __floats2half2_rn(vb.z, vb.w);
    uint4 o;
    o.x = *(unsigned*)&h0;
    o.y = *(unsigned*)&h1;
    o.z = *(unsigned*)&h2;
    o.w = *(unsigned*)&h3;
    h16b[i] = o;
    uint2 o8;
    o8.x = pack_f8x4(va.x, va.y, va.z, va.w);
    o8.y = pack_f8x4(vb.x, vb.y, vb.z, vb.w);
    x8[i] = o8;
}

__device__ __forceinline__ unsigned encode_cv(int col, float val)
{
    float w = 0.225f * val;
    int q = __float2int_rn(w * (WQ_SCALE / W_MAX));
    q = min(max(q, 0), (int)WQ_SCALE);
    return ((unsigned)col & COL_MASK) | ((unsigned)q << 18);
}

// ---- single-pass bucketed CSR fill: 16 edges/thread ----
__global__ __launch_bounds__(256) void fill_kernel(
    const int* __restrict__ ei, const float* __restrict__ ev, int E,
    int* __restrict__ len, unsigned* __restrict__ cv)
{
    int base = (blockIdx.x * blockDim.x + threadIdx.x) * 16;
    if (base >= E) return;

    if (base + 15 < E) {
        int rows[16], cols[16];
        float w[16];
        #pragma unroll
        for (int q = 0; q < 4; q++) {
            int4 r = *(const int4*)(ei + base + 4 * q);
            rows[4*q+0]=r.x; rows[4*q+1]=r.y; rows[4*q+2]=r.z; rows[4*q+3]=r.w;
        }
        #pragma unroll
        for (int q = 0; q < 4; q++) {
            int4 c = *(const int4*)(ei + E + base + 4 * q);
            cols[4*q+0]=c.x; cols[4*q+1]=c.y; cols[4*q+2]=c.z; cols[4*q+3]=c.w;
        }
        #pragma unroll
        for (int q = 0; q < 4; q++) {
            float4 v = *(const float4*)(ev + base + 4 * q);
            w[4*q+0]=v.x; w[4*q+1]=v.y; w[4*q+2]=v.z; w[4*q+3]=v.w;
        }
        #pragma unroll
        for (int j = 0; j < 16; j++) {
            if ((unsigned)rows[j] >= N_NODES || (unsigned)cols[j] >= N_NODES) continue;
            int slot = atomicAdd(&len[rows[j]], 1);
            if (slot < ROW_CAP)
                cv[((size_t)rows[j] << 6) + slot] = encode_cv(cols[j], w[j]);
        }
    } else {
        for (int e = base; e < E; e++) {
            int row = ei[e], col = ei[E + e];
            if ((unsigned)row >= N_NODES || (unsigned)col >= N_NODES) continue;
            int slot = atomicAdd(&len[row], 1);
            if (slot < ROW_CAP)
                cv[((size_t)row << 6) + slot] = encode_cv(col, ev[e]);
        }
    }
}

// Accumulate one edge into 8-float accumulator; predicated gather.
__device__ __forceinline__ void acc_edge(
    float* a, const uint4* __restrict__ h4, unsigned enc, bool valid, int sub)
{
    unsigned col = enc & COL_MASK;
    float w = (float)(enc >> 18) * (W_MAX / WQ_SCALE);
    uint4 v = make_uint4(0u, 0u, 0u, 0u);
    if (valid) v = __ldg(&h4[(((size_t)col) << 4) + sub]);
    float2 p;
    p = __half22float2(*(__half2*)&v.x); a[0] = fmaf(w, p.x, a[0]); a[1] = fmaf(w, p.y, a[1]);
    p = __half22float2(*(__half2*)&v.y); a[2] = fmaf(w, p.x, a[2]); a[3] = fmaf(w, p.y, a[3]);
    p = __half22float2(*(__half2*)&v.z); a[4] = fmaf(w, p.x, a[4]); a[5] = fmaf(w, p.y, a[5]);
    p = __half22float2(*(__half2*)&v.w); a[6] = fmaf(w, p.x, a[6]); a[7] = fmaf(w, p.y, a[7]);
}

// ---- SpMM: TWO rows per warp. OUTM: 1 = fp16 store, 2 = fp32 final ----
template<int OUTM>
__global__ __launch_bounds__(256) void spmm2_kernel(
    const int*      __restrict__ len,
    const unsigned* __restrict__ cv,
    const uint4*    __restrict__ h4,
    const uint2*    __restrict__ x8,   // fp8 alpha source (additive term)
    void*           __restrict__ dst,
    float alpha_k)
{
    int warp_global = (blockIdx.x * blockDim.x + threadIdx.x) >> 5;
    int lane = threadIdx.x & 31;
    int sub  = lane & 15;                 // 16B chunk within the 256B row
    int row  = (warp_global << 1) + (lane >> 4);
    if (row >= N_NODES) return;

    int L = min(len[row], ROW_CAP);
    int Lo = __shfl_xor_sync(0xffffffffu, L, 16);
    int Lmax = max(L, Lo);

    const unsigned* cvrow = cv + ((size_t)row << 6);
    size_t hidx = (((size_t)row) << 4) + sub;

    // alpha * x from the fp8 copy (additive term)
    float a[8];
    {
        uint2 xv = __ldg(&x8[hidx]);
        float4 f0 = unpack_f8x4(xv.x);
        float4 f1 = unpack_f8x4(xv.y);
        a[0] = alpha_k * f0.x; a[1] = alpha_k * f0.y;
        a[2] = alpha_k * f0.z; a[3] = alpha_k * f0.w;
        a[4] = alpha_k * f1.x; a[5] = alpha_k * f1.y;
        a[6] = alpha_k * f1.z; a[7] = alpha_k * f1.w;
    }

    int i = 0;
    for (; i + 3 < Lmax; i += 4) {
        uint4 e = __ldg((const uint4*)(cvrow + i));
        acc_edge(a, h4, e.x, (i + 0) < L, sub);
        acc_edge(a, h4, e.y, (i + 1) < L, sub);
        acc_edge(a, h4, e.z, (i + 2) < L, sub);
        acc_edge(a, h4, e.w, (i + 3) < L, sub);
    }
    for (; i < Lmax; i++) {
        unsigned e = __ldg(cvrow + i);
        acc_edge(a, h4, e, i < L, sub);
    }

    if constexpr (OUTM == 1) {
        __half2 h0 = __floats2half2_rn(a[0], a[1]);
        __half2 h1 = __floats2half2_rn(a[2], a[3]);
        __half2 h2 = __floats2half2_rn(a[4], a[5]);
        __half2 h3 = __floats2half2_rn(a[6], a[7]);
        uint4 o;
        o.x = *(unsigned*)&h0;
        o.y = *(unsigned*)&h1;
        o.z = *(unsigned*)&h2;
        o.w = *(unsigned*)&h3;
        ((uint4*)dst)[hidx] = o;
    } else {
        // acc already includes alpha_10 * x; scale to physical units.
        const float SCALE = 1048576.0f;   // 4^10
        float4 o0, o1;
        o0.x = SCALE * a[0]; o0.y = SCALE * a[1];
        o0.z = SCALE * a[2]; o0.w = SCALE * a[3];
        o1.x = SCALE * a[4]; o1.y = SCALE * a[5];
        o1.z = SCALE * a[6]; o1.w = SCALE * a[7];
        float4* out4 = (float4*)dst;
        size_t obase = ((size_t)row) * 32 + sub * 2;
        out4[obase]     = o0;
        out4[obase + 1] = o1;
    }
}

extern "C" void kernel_launch(void* const* d_in, const int* in_sizes, int n_in,
                              void* d_out, int out_size)
{
    const float* x  = (const float*)d_in[0];
    const int*   ei = (const int*)d_in[1];
    const float* ev = (const float*)d_in[2];
    float* out      = (float*)d_out;

    const int E  = in_sizes[2];
    const int n8 = in_sizes[0] / 8;

    void *p16a, *p16b, *px8, *pl, *pcv;
    cudaGetSymbolAddress(&p16a, g_h16a);
    cudaGetSymbolAddress(&p16b, g_h16b);
    cudaGetSymbolAddress(&px8, g_x8);
    cudaGetSymbolAddress(&pl, g_len);
    cudaGetSymbolAddress(&pcv, g_cv);
    uint4*    h16a = (uint4*)p16a;
    uint4*    h16b = (uint4*)p16b;
    uint2*    x8   = (uint2*)px8;
    int*      len  = (int*)pl;
    unsigned* cv   = (unsigned*)pcv;

    const int e16blocks  = ((E + 15) / 16 + 255) / 256;
    const int cvt_blocks = (n8 + 255) / 256;
    const int spmm_blocks = (N_NODES + 15) / 16;   // 2 rows/warp, 16 rows/block

    // convert: fp16(x) -> h16b (iteration-1 gather source), fp8(x) -> x8
    convert_x_kernel<<<cvt_blocks, 256>>>((const float4*)x, h16b, x8, len, n8);
    fill_kernel<<<e16blocks, 256>>>(ei, ev, E, len, cv);

    // Two-buffer chain (x16 eliminated; footprint 70MB < L2):
    //   iter1: h16b -> h16a   iter2: h16a -> h16b   ... alternating ...
    //   iter9: h16b -> h16a   iter10: h16a -> out (fp32)
    // alpha_k = 0.1 * 4^-k (stored_k = h_k * 4^-k).
    spmm2_kernel<1><<<spmm_blocks, 256>>>(len, cv, h16b, x8, h16a, 0.1f * 0.25f);
    spmm2_kernel<1><<<spmm_blocks, 256>>>(len, cv, h16a, x8, h16b, 0.1f * 0.0625f);
    spmm2_kernel<1><<<spmm_blocks, 256>>>(len, cv, h16b, x8, h16a, 0.1f * 0.015625f);
    spmm2_kernel<1><<<spmm_blocks, 256>>>(len, cv, h16a, x8, h16b, 0.1f * 0.00390625f);
    spmm2_kernel<1><<<spmm_blocks, 256>>>(len, cv, h16b, x8, h16a, 0.1f * 0.0009765625f);
    spmm2_kernel<1><<<spmm_blocks, 256>>>(len, cv, h16a, x8, h16b, 0.1f * 0.000244140625f);
    spmm2_kernel<1><<<spmm_blocks, 256>>>(len, cv, h16b, x8, h16a, 0.1f * 6.103515625e-05f);
    spmm2_kernel<1><<<spmm_blocks, 256>>>(len, cv, h16a, x8, h16b, 0.1f * 1.52587890625e-05f);
    spmm2_kernel<1><<<spmm_blocks, 256>>>(len, cv, h16b, x8, h16a, 0.1f * 3.814697265625e-06f);
    // final: alpha_10 = 0.1 * 4^-10 (SCALE*acc restores ... + 0.1*x)
    spmm2_kernel<2><<<spmm_blocks, 256>>>(len, cv, h16a, x8, out, 0.1f * 9.5367431640625e-07f);
}